// round 1
// baseline (speedup 1.0000x reference)
#include <cuda_runtime.h>
#include <cstdint>

// ---------------------------------------------------------------------------
// DSDMSR multi-scale SRCNN cascade, fp32 baseline.
// Layouts:
//   image: [2][1][64][64]
//   w1: [17][64][1][9][9]  b1: [17][64]
//   w2: [17][32][64][5][5] b2: [17][32]
//   w3: [17][1][32][5][5]  b3: [17][1]
// Output (concatenated): out_x2 (2,1,128,128) | out_x4 (2,1,256,256) |
//   out_x8 (2,1,512,512) | out_x16 (2,1,1024,1024) | msf (2,1,1024,1024)
// ---------------------------------------------------------------------------

// Scratch (device globals; allocation-free rule).
// t1: max(2*4*64*512*512, 2*1*64*1024*1024) = 134217728 floats (512 MB)
// t2: max(2*4*32*512*512, 2*1*32*1024*1024) = 67108864  floats (256 MB)
__device__ float g_t1[134217728];
__device__ float g_t2[67108864];
__device__ float g_msf[2 * 1024 * 1024];
__device__ float g_w1t[17 * 81 * 64];        // [u][tap][oc]
__device__ float g_w2t[17 * 64 * 25 * 32];   // [u][ic][tap][oc]

// ---------------------------------------------------------------------------
// Weight transpose: coalesced smem loads later.
// ---------------------------------------------------------------------------
__global__ void prep_weights_kernel(const float* __restrict__ w1,
                                    const float* __restrict__ w2) {
    int idx = blockIdx.x * 256 + threadIdx.x;
    if (idx < 17 * 81 * 64) {
        int u = idx / (81 * 64);
        int r = idx - u * 81 * 64;
        int tap = r / 64;
        int oc = r - tap * 64;
        g_w1t[idx] = w1[(u * 64 + oc) * 81 + tap];
    }
    if (idx < 17 * 64 * 25 * 32) {
        int u = idx / (64 * 25 * 32);
        int r = idx - u * 64 * 25 * 32;
        int ic = r / (25 * 32);
        int r2 = r - ic * 25 * 32;
        int tap = r2 / 32;
        int oc = r2 - tap * 32;
        g_w2t[idx] = w2[((u * 32 + oc) * 64 + ic) * 25 + tap];
    }
}

// ---------------------------------------------------------------------------
// conv1: 9x9, 1 -> 64, ReLU.  Block: 256 thr, 16x16 px tile, all 64 oc.
// Thread: 4 px (x-consecutive) x 16 oc.
// grid: (W/16, H/16, 2*nu)
// ---------------------------------------------------------------------------
__global__ __launch_bounds__(256) void conv1_kernel(
    const float* __restrict__ in,    // [2][H][W]
    const float* __restrict__ wt,    // [nu][81][64]  (base pre-offset per stage)
    const float* __restrict__ bias,  // [nu][64]
    float* __restrict__ out,         // [2*nu][64][H][W]
    int H, int W, int nu)
{
    __shared__ float s_in[24 * 24];
    __shared__ float s_w[81 * 64];

    int z = blockIdx.z;
    int u = z % nu;
    int b = z / nu;
    int tid = threadIdx.x;
    int x0 = blockIdx.x * 16, y0 = blockIdx.y * 16;
    const float* inb = in + (size_t)b * H * W;
    const float* wu = wt + (size_t)u * 5184;

    for (int i = tid; i < 576; i += 256) {
        int iy = i / 24, ix = i - iy * 24;
        int gy = y0 + iy - 4, gx = x0 + ix - 4;
        float v = 0.f;
        if (gy >= 0 && gy < H && gx >= 0 && gx < W) v = inb[(size_t)gy * W + gx];
        s_in[i] = v;
    }
    for (int i = tid; i < 5184; i += 256) s_w[i] = wu[i];
    __syncthreads();

    int ocg = tid >> 6;            // 0..3 (16 oc each)
    int pt = tid & 63;
    int row = pt >> 2;             // 0..15
    int cgx = (pt & 3) * 4;        // 0,4,8,12

    float acc[4][16];
#pragma unroll
    for (int j = 0; j < 4; j++)
#pragma unroll
        for (int c = 0; c < 16; c++) acc[j][c] = 0.f;

    for (int dy = 0; dy < 9; dy++) {
        const float* ipb = &s_in[(row + dy) * 24 + cgx];
        const float* wpb = &s_w[dy * 9 * 64 + ocg * 16];
#pragma unroll
        for (int dx = 0; dx < 9; dx++) {
            float iv[4];
#pragma unroll
            for (int j = 0; j < 4; j++) iv[j] = ipb[dx + j];
            const float* wp = wpb + dx * 64;
            float4 w0 = *(const float4*)(wp);
            float4 w1v = *(const float4*)(wp + 4);
            float4 w2v = *(const float4*)(wp + 8);
            float4 w3v = *(const float4*)(wp + 12);
            float wv[16] = {w0.x, w0.y, w0.z, w0.w, w1v.x, w1v.y, w1v.z, w1v.w,
                            w2v.x, w2v.y, w2v.z, w2v.w, w3v.x, w3v.y, w3v.z, w3v.w};
#pragma unroll
            for (int j = 0; j < 4; j++)
#pragma unroll
                for (int c = 0; c < 16; c++) acc[j][c] += iv[j] * wv[c];
        }
    }

    int y = y0 + row;
    int xb = x0 + cgx;
#pragma unroll
    for (int c = 0; c < 16; c++) {
        int oc = ocg * 16 + c;
        float bv = bias[u * 64 + oc];
        float4 v;
        v.x = fmaxf(acc[0][c] + bv, 0.f);
        v.y = fmaxf(acc[1][c] + bv, 0.f);
        v.z = fmaxf(acc[2][c] + bv, 0.f);
        v.w = fmaxf(acc[3][c] + bv, 0.f);
        *(float4*)(out + ((size_t)z * 64 + oc) * H * W + (size_t)y * W + xb) = v;
    }
}

// ---------------------------------------------------------------------------
// conv2: 5x5, 64 -> 32, ReLU.  Block: 128 thr, 16x16 px tile, 32 oc.
// Thread: 8 px (x-consecutive) x 8 oc.  ic processed in chunks of 8.
// grid: (W/16, H/16, 2*nu)
// ---------------------------------------------------------------------------
__global__ __launch_bounds__(128) void conv2_kernel(
    const float* __restrict__ in,    // [2*nu][64][H][W]
    const float* __restrict__ wt,    // [nu][64][25][32]
    const float* __restrict__ bias,  // [nu][32]
    float* __restrict__ out,         // [2*nu][32][H][W]
    int H, int W, int nu)
{
    __shared__ float s_in[8][400];   // 8 ic x 20x20 halo
    __shared__ float s_w[8 * 25 * 32];

    int z = blockIdx.z;
    int u = z % nu;
    int tid = threadIdx.x;
    int x0 = blockIdx.x * 16, y0 = blockIdx.y * 16;
    const float* inz = in + (size_t)z * 64 * H * W;
    const float* wu = wt + (size_t)u * 51200;

    int ocg = tid >> 5;              // 0..3 (8 oc each); warp-uniform
    int p = tid & 31;
    int row = p >> 1;                // 0..15
    int colg = (p & 1) * 8;          // 0 or 8

    float acc[8][8];
#pragma unroll
    for (int j = 0; j < 8; j++)
#pragma unroll
        for (int k = 0; k < 8; k++) acc[j][k] = 0.f;

    for (int icb = 0; icb < 64; icb += 8) {
        __syncthreads();
#pragma unroll
        for (int l = 0; l < 25; l++) {           // 3200 / 128
            int i = tid + l * 128;
            int ic = i / 400;
            int r = i - ic * 400;
            int iy = r / 20, ix = r - iy * 20;
            int gy = y0 + iy - 2, gx = x0 + ix - 2;
            float v = 0.f;
            if (gy >= 0 && gy < H && gx >= 0 && gx < W)
                v = inz[(size_t)(icb + ic) * H * W + (size_t)gy * W + gx];
            s_in[ic][r] = v;
        }
#pragma unroll
        for (int l = 0; l < 50; l++)             // 6400 / 128, contiguous
            s_w[tid + l * 128] = wu[icb * 800 + tid + l * 128];
        __syncthreads();

        for (int ic = 0; ic < 8; ic++) {
            for (int dy = 0; dy < 5; dy++) {
                const float* ipb = &s_in[ic][(row + dy) * 20 + colg];
                const float* wpb = &s_w[(ic * 25 + dy * 5) * 32 + ocg * 8];
#pragma unroll
                for (int dx = 0; dx < 5; dx++) {
                    float4 wa = *(const float4*)(wpb + dx * 32);
                    float4 wb = *(const float4*)(wpb + dx * 32 + 4);
                    float wv[8] = {wa.x, wa.y, wa.z, wa.w, wb.x, wb.y, wb.z, wb.w};
                    float iv[8];
#pragma unroll
                    for (int j = 0; j < 8; j++) iv[j] = ipb[dx + j];
#pragma unroll
                    for (int j = 0; j < 8; j++)
#pragma unroll
                        for (int k = 0; k < 8; k++) acc[j][k] += iv[j] * wv[k];
                }
            }
        }
    }

    int y = y0 + row;
    int xb = x0 + colg;
#pragma unroll
    for (int k = 0; k < 8; k++) {
        int oc = ocg * 8 + k;
        float bv = bias[u * 32 + oc];
        float4 o0, o1;
        o0.x = fmaxf(acc[0][k] + bv, 0.f);
        o0.y = fmaxf(acc[1][k] + bv, 0.f);
        o0.z = fmaxf(acc[2][k] + bv, 0.f);
        o0.w = fmaxf(acc[3][k] + bv, 0.f);
        o1.x = fmaxf(acc[4][k] + bv, 0.f);
        o1.y = fmaxf(acc[5][k] + bv, 0.f);
        o1.z = fmaxf(acc[6][k] + bv, 0.f);
        o1.w = fmaxf(acc[7][k] + bv, 0.f);
        float* op = out + ((size_t)z * 32 + oc) * H * W + (size_t)y * W + xb;
        *(float4*)op = o0;
        *(float4*)(op + 4) = o1;
    }
}

// ---------------------------------------------------------------------------
// conv3: 5x5, 32 -> 1, no ReLU, optional 2x2 interleaved scatter.
// Block: 256 thr, 16x16 px tile, 1 px/thread.
// grid: (W/16, H/16, 2*nu)
// ---------------------------------------------------------------------------
__global__ __launch_bounds__(256) void conv3_kernel(
    const float* __restrict__ in,    // [2*nu][32][H][W]
    const float* __restrict__ w3,    // [nu][32][25]  (native layout of w3)
    const float* __restrict__ b3,    // [nu]
    float* __restrict__ out,
    int H, int W, int nu, int interleave)
{
    __shared__ float s_in[16][400];
    __shared__ float s_w[16 * 25];

    int z = blockIdx.z;
    int u = z % nu;
    int b = z / nu;
    int tid = threadIdx.x;
    int x0 = blockIdx.x * 16, y0 = blockIdx.y * 16;
    int ty = tid >> 4, tx = tid & 15;
    const float* inz = in + (size_t)z * 32 * H * W;

    float acc = b3[u];

    for (int icb = 0; icb < 32; icb += 16) {
        __syncthreads();
        for (int i = tid; i < 6400; i += 256) {
            int ic = i / 400;
            int r = i - ic * 400;
            int iy = r / 20, ix = r - iy * 20;
            int gy = y0 + iy - 2, gx = x0 + ix - 2;
            float v = 0.f;
            if (gy >= 0 && gy < H && gx >= 0 && gx < W)
                v = inz[(size_t)(icb + ic) * H * W + (size_t)gy * W + gx];
            s_in[ic][r] = v;
        }
        for (int i = tid; i < 400; i += 256)
            s_w[i] = w3[(size_t)u * 800 + icb * 25 + i];
        __syncthreads();

        for (int ic = 0; ic < 16; ic++) {
#pragma unroll
            for (int dy = 0; dy < 5; dy++)
#pragma unroll
                for (int dx = 0; dx < 5; dx++)
                    acc += s_in[ic][(ty + dy) * 20 + tx + dx] * s_w[ic * 25 + dy * 5 + dx];
        }
    }

    int y = y0 + ty, x = x0 + tx;
    if (interleave) {
        int uy = u >> 1, ux = u & 1;
        out[(size_t)b * 4 * H * W + (size_t)(2 * y + uy) * (2 * W) + 2 * x + ux] = acc;
    } else {
        out[(size_t)b * H * W + (size_t)y * W + x] = acc;
    }
}

// ---------------------------------------------------------------------------
// msf_in = up8(x2) + up4(x4) + up2(x8) + x16   (bilinear, half-pixel, clamp)
// ---------------------------------------------------------------------------
__device__ __forceinline__ float bilin(const float* __restrict__ p, int N,
                                       float inv_s, int y, int x) {
    float sy = (y + 0.5f) * inv_s - 0.5f;
    float sx = (x + 0.5f) * inv_s - 0.5f;
    float fy0 = floorf(sy), fx0 = floorf(sx);
    float fy = sy - fy0, fx = sx - fx0;
    int y0 = (int)fy0, x0 = (int)fx0;
    int y0c = min(max(y0, 0), N - 1);
    int y1c = min(max(y0 + 1, 0), N - 1);
    int x0c = min(max(x0, 0), N - 1);
    int x1c = min(max(x0 + 1, 0), N - 1);
    float v00 = p[(size_t)y0c * N + x0c];
    float v01 = p[(size_t)y0c * N + x1c];
    float v10 = p[(size_t)y1c * N + x0c];
    float v11 = p[(size_t)y1c * N + x1c];
    return (1.f - fy) * ((1.f - fx) * v00 + fx * v01) +
           fy * ((1.f - fx) * v10 + fx * v11);
}

__global__ void msf_in_kernel(const float* __restrict__ x2,
                              const float* __restrict__ x4,
                              const float* __restrict__ x8,
                              const float* __restrict__ x16,
                              float* __restrict__ out) {
    int idx = blockIdx.x * 256 + threadIdx.x;
    if (idx >= 2 * 1024 * 1024) return;
    int b = idx >> 20;
    int r = idx & 0xFFFFF;
    int y = r >> 10, x = r & 1023;
    float v = x16[idx];
    v += bilin(x2 + (size_t)b * 128 * 128, 128, 0.125f, y, x);
    v += bilin(x4 + (size_t)b * 256 * 256, 256, 0.25f, y, x);
    v += bilin(x8 + (size_t)b * 512 * 512, 512, 0.5f, y, x);
    out[idx] = v;
}

// ---------------------------------------------------------------------------
// Host orchestration
// ---------------------------------------------------------------------------
extern "C" void kernel_launch(void* const* d_in, const int* in_sizes, int n_in,
                              void* d_out, int out_size) {
    const float* image = (const float*)d_in[0];
    const float* w1 = (const float*)d_in[1];
    const float* b1 = (const float*)d_in[2];
    const float* w2 = (const float*)d_in[3];
    const float* b2 = (const float*)d_in[4];
    const float* w3 = (const float*)d_in[5];
    const float* b3 = (const float*)d_in[6];
    float* out = (float*)d_out;

    float *t1, *t2, *msf, *w1t, *w2t;
    cudaGetSymbolAddress((void**)&t1, g_t1);
    cudaGetSymbolAddress((void**)&t2, g_t2);
    cudaGetSymbolAddress((void**)&msf, g_msf);
    cudaGetSymbolAddress((void**)&w1t, g_w1t);
    cudaGetSymbolAddress((void**)&w2t, g_w2t);

    prep_weights_kernel<<<(17 * 64 * 25 * 32 + 255) / 256, 256>>>(w1, w2);

    float* ox2 = out + 0;
    float* ox4 = out + 32768;     // + 2*128*128
    float* ox8 = out + 163840;    // + 2*256*256
    float* ox16 = out + 688128;   // + 2*512*512
    float* omsf = out + 2785280;  // + 2*1024*1024

    auto run_stage = [&](const float* inp, int H, int W, int ubase,
                         float* outp, int nu, int il) {
        dim3 g(W / 16, H / 16, 2 * nu);
        conv1_kernel<<<g, 256>>>(inp, w1t + (size_t)ubase * 5184,
                                 b1 + (size_t)ubase * 64, t1, H, W, nu);
        conv2_kernel<<<g, 128>>>(t1, w2t + (size_t)ubase * 51200,
                                 b2 + (size_t)ubase * 32, t2, H, W, nu);
        conv3_kernel<<<g, 256>>>(t2, w3 + (size_t)ubase * 800,
                                 b3 + ubase, outp, H, W, nu, il);
    };

    run_stage(image, 64, 64, 0, ox2, 4, 1);
    run_stage(ox2, 128, 128, 4, ox4, 4, 1);
    run_stage(ox4, 256, 256, 8, ox8, 4, 1);
    run_stage(ox8, 512, 512, 12, ox16, 4, 1);

    msf_in_kernel<<<(2 * 1024 * 1024) / 256, 256>>>(ox2, ox4, ox8, ox16, msf);

    run_stage(msf, 1024, 1024, 16, omsf, 1, 0);
}

// round 2
// speedup vs baseline: 1.9980x; 1.9980x over previous
#include <cuda_runtime.h>
#include <cstdint>

// ---------------------------------------------------------------------------
// DSDMSR multi-scale SRCNN cascade.
// conv1 (9x9, 1->64) fp32; conv2 (5x5, 64->32) TF32 tensor-core mma; conv3 fp32.
// ---------------------------------------------------------------------------

__device__ float g_t1[134217728];            // conv1 out scratch (512 MB)
__device__ float g_t2[67108864];             // conv2 out scratch (256 MB)
__device__ float g_msf[2 * 1024 * 1024];
__device__ float g_w1t[17 * 81 * 64];        // [u][tap][oc]
__device__ float g_w2t[17 * 64 * 25 * 32];   // [u][ic][tap][oc], TF32-rounded

__device__ __forceinline__ float tf32r(float x) {
    unsigned r;
    asm("cvt.rna.tf32.f32 %0, %1;" : "=r"(r) : "f"(x));
    return __uint_as_float(r);
}

// ---------------------------------------------------------------------------
// Weight prep: transpose + TF32 rounding for w2.
// ---------------------------------------------------------------------------
__global__ void prep_weights_kernel(const float* __restrict__ w1,
                                    const float* __restrict__ w2) {
    int idx = blockIdx.x * 256 + threadIdx.x;
    if (idx < 17 * 81 * 64) {
        int u = idx / (81 * 64);
        int r = idx - u * 81 * 64;
        int tap = r / 64;
        int oc = r - tap * 64;
        g_w1t[idx] = w1[(u * 64 + oc) * 81 + tap];
    }
    if (idx < 17 * 64 * 25 * 32) {
        int u = idx / (64 * 25 * 32);
        int r = idx - u * 64 * 25 * 32;
        int ic = r / (25 * 32);
        int r2 = r - ic * 25 * 32;
        int tap = r2 / 32;
        int oc = r2 - tap * 32;
        g_w2t[idx] = tf32r(w2[((u * 32 + oc) * 64 + ic) * 25 + tap]);
    }
}

// ---------------------------------------------------------------------------
// conv1: 9x9, 1 -> 64, ReLU; outputs rounded to TF32 (consumed by conv2 mma).
// ---------------------------------------------------------------------------
__global__ __launch_bounds__(256) void conv1_kernel(
    const float* __restrict__ in, const float* __restrict__ wt,
    const float* __restrict__ bias, float* __restrict__ out,
    int H, int W, int nu)
{
    __shared__ float s_in[24 * 24];
    __shared__ float s_w[81 * 64];

    int z = blockIdx.z;
    int u = z % nu;
    int b = z / nu;
    int tid = threadIdx.x;
    int x0 = blockIdx.x * 16, y0 = blockIdx.y * 16;
    const float* inb = in + (size_t)b * H * W;
    const float* wu = wt + (size_t)u * 5184;

    for (int i = tid; i < 576; i += 256) {
        int iy = i / 24, ix = i - iy * 24;
        int gy = y0 + iy - 4, gx = x0 + ix - 4;
        float v = 0.f;
        if (gy >= 0 && gy < H && gx >= 0 && gx < W) v = inb[(size_t)gy * W + gx];
        s_in[i] = v;
    }
    for (int i = tid; i < 5184; i += 256) s_w[i] = wu[i];
    __syncthreads();

    int ocg = tid >> 6;
    int pt = tid & 63;
    int row = pt >> 2;
    int cgx = (pt & 3) * 4;

    float acc[4][16];
#pragma unroll
    for (int j = 0; j < 4; j++)
#pragma unroll
        for (int c = 0; c < 16; c++) acc[j][c] = 0.f;

    for (int dy = 0; dy < 9; dy++) {
        const float* ipb = &s_in[(row + dy) * 24 + cgx];
        const float* wpb = &s_w[dy * 9 * 64 + ocg * 16];
#pragma unroll
        for (int dx = 0; dx < 9; dx++) {
            float iv[4];
#pragma unroll
            for (int j = 0; j < 4; j++) iv[j] = ipb[dx + j];
            const float* wp = wpb + dx * 64;
            float4 w0 = *(const float4*)(wp);
            float4 w1v = *(const float4*)(wp + 4);
            float4 w2v = *(const float4*)(wp + 8);
            float4 w3v = *(const float4*)(wp + 12);
            float wv[16] = {w0.x, w0.y, w0.z, w0.w, w1v.x, w1v.y, w1v.z, w1v.w,
                            w2v.x, w2v.y, w2v.z, w2v.w, w3v.x, w3v.y, w3v.z, w3v.w};
#pragma unroll
            for (int j = 0; j < 4; j++)
#pragma unroll
                for (int c = 0; c < 16; c++) acc[j][c] += iv[j] * wv[c];
        }
    }

    int y = y0 + row;
    int xb = x0 + cgx;
#pragma unroll
    for (int c = 0; c < 16; c++) {
        int oc = ocg * 16 + c;
        float bv = bias[u * 64 + oc];
        float4 v;
        v.x = tf32r(fmaxf(acc[0][c] + bv, 0.f));
        v.y = tf32r(fmaxf(acc[1][c] + bv, 0.f));
        v.z = tf32r(fmaxf(acc[2][c] + bv, 0.f));
        v.w = tf32r(fmaxf(acc[3][c] + bv, 0.f));
        *(float4*)(out + ((size_t)z * 64 + oc) * H * W + (size_t)y * W + xb) = v;
    }
}

// ---------------------------------------------------------------------------
// conv2: 5x5, 64 -> 32, ReLU via TF32 mma.sync.m16n8k8.
// Block 256 thr (8 warps), 16x16 px tile, 32 oc.
// Each warp: 32 oc x 32 px (rows 2*warp, 2*warp+1) = 2 M-tiles x 4 N-tiles.
// K = ic-chunks of 8, 25 taps per chunk (K=8 per mma: the 8 ic of the chunk).
// ---------------------------------------------------------------------------
#define RAW_STRIDE 408   // 400 used (20x20), pad for bank spread (408%32=24)
#define W_STRIDE   808   // 800 used (25x32), pad for bank spread (808%32=8)

__device__ __forceinline__ void mma_tf32(float c[4], const unsigned a[4],
                                         unsigned b0, unsigned b1) {
    asm volatile(
        "mma.sync.aligned.m16n8k8.row.col.f32.tf32.tf32.f32 "
        "{%0,%1,%2,%3}, {%4,%5,%6,%7}, {%8,%9}, {%0,%1,%2,%3};"
        : "+f"(c[0]), "+f"(c[1]), "+f"(c[2]), "+f"(c[3])
        : "r"(a[0]), "r"(a[1]), "r"(a[2]), "r"(a[3]), "r"(b0), "r"(b1));
}

__global__ __launch_bounds__(256) void conv2_mma_kernel(
    const float* __restrict__ in,    // [2*nu][64][H][W] (tf32-rounded values)
    const float* __restrict__ wt,    // [nu][64][25][32] tf32-rounded
    const float* __restrict__ bias,  // [nu][32]
    float* __restrict__ out,         // [2*nu][32][H][W]
    int H, int W, int nu)
{
    __shared__ float s_raw[8 * RAW_STRIDE];
    __shared__ float s_w[8 * W_STRIDE];

    int z = blockIdx.z;
    int u = z % nu;
    int tid = threadIdx.x;
    int warp = tid >> 5;
    int lane = tid & 31;
    int x0 = blockIdx.x * 16, y0 = blockIdx.y * 16;
    const float* inz = in + (size_t)z * 64 * H * W;
    const float* wu = wt + (size_t)u * 51200;

    int r0 = warp * 2;          // this warp's first px row in the 16x16 tile
    int lq = lane & 3;          // quad-lane (k index / C-col group)
    int lr = lane >> 2;         // 0..7

    // B-fragment smem base per N-tile (add ic*RAW_STRIDE + dy*20+dx later)
    int bbase[4];
#pragma unroll
    for (int j = 0; j < 4; j++)
        bbase[j] = lq * RAW_STRIDE + (r0 + (j >> 1)) * 20 + (j & 1) * 8 + lr;

    // A-fragment smem base (add t*32 later)
    int abase = lq * W_STRIDE + lr;

    float c[2][4][4];
#pragma unroll
    for (int m = 0; m < 2; m++)
#pragma unroll
        for (int j = 0; j < 4; j++)
#pragma unroll
            for (int q = 0; q < 4; q++) c[m][j][q] = 0.f;

    for (int icb = 0; icb < 64; icb += 8) {
        __syncthreads();
        // load raw input tile: 8 ic x 20x20 (halo 2)
#pragma unroll
        for (int l = 0; l < 13; l++) {
            int i = tid + l * 256;
            if (i < 3200) {
                int ic = i / 400;
                int r = i - ic * 400;
                int iy = r / 20, ix = r - iy * 20;
                int gy = y0 + iy - 2, gx = x0 + ix - 2;
                float v = 0.f;
                if (gy >= 0 && gy < H && gx >= 0 && gx < W)
                    v = inz[(size_t)(icb + ic) * H * W + (size_t)gy * W + gx];
                s_raw[ic * RAW_STRIDE + r] = v;
            }
        }
        // load weights: 8 ic x 25 taps x 32 oc (contiguous in global)
#pragma unroll
        for (int l = 0; l < 25; l++) {
            int i = tid + l * 256;
            int ic = i / 800;
            int r = i - ic * 800;
            s_w[ic * W_STRIDE + r] = wu[icb * 800 + i];
        }
        __syncthreads();

#pragma unroll
        for (int dy = 0; dy < 5; dy++) {
#pragma unroll
            for (int dx = 0; dx < 5; dx++) {
                const int t = dy * 5 + dx;
                const int toff = dy * 20 + dx;
                const float* wp = s_w + abase + t * 32;
                unsigned a[2][4];
#pragma unroll
                for (int m = 0; m < 2; m++) {
                    a[m][0] = __float_as_uint(wp[m * 16]);
                    a[m][1] = __float_as_uint(wp[m * 16 + 8]);
                    a[m][2] = __float_as_uint(wp[m * 16 + 4 * W_STRIDE]);
                    a[m][3] = __float_as_uint(wp[m * 16 + 4 * W_STRIDE + 8]);
                }
#pragma unroll
                for (int j = 0; j < 4; j++) {
                    unsigned b0 = __float_as_uint(s_raw[bbase[j] + toff]);
                    unsigned b1 = __float_as_uint(s_raw[bbase[j] + 4 * RAW_STRIDE + toff]);
                    mma_tf32(c[0][j], a[0], b0, b1);
                    mma_tf32(c[1][j], a[1], b0, b1);
                }
            }
        }
    }

    // epilogue: oc = m*16 + lr (+8), y = y0 + r0 + (j>>1), x = x0 + (j&1)*8 + 2*lq
#pragma unroll
    for (int m = 0; m < 2; m++) {
        int oc0 = m * 16 + lr;
        float bv0 = bias[u * 32 + oc0];
        float bv1 = bias[u * 32 + oc0 + 8];
#pragma unroll
        for (int j = 0; j < 4; j++) {
            int y = y0 + r0 + (j >> 1);
            int x = x0 + (j & 1) * 8 + 2 * lq;
            float2 v0, v1;
            v0.x = fmaxf(c[m][j][0] + bv0, 0.f);
            v0.y = fmaxf(c[m][j][1] + bv0, 0.f);
            v1.x = fmaxf(c[m][j][2] + bv1, 0.f);
            v1.y = fmaxf(c[m][j][3] + bv1, 0.f);
            *(float2*)(out + ((size_t)z * 32 + oc0) * H * W + (size_t)y * W + x) = v0;
            *(float2*)(out + ((size_t)z * 32 + oc0 + 8) * H * W + (size_t)y * W + x) = v1;
        }
    }
}

// ---------------------------------------------------------------------------
// conv3: 5x5, 32 -> 1, no ReLU, optional 2x2 interleaved scatter.
// ---------------------------------------------------------------------------
__global__ __launch_bounds__(256) void conv3_kernel(
    const float* __restrict__ in, const float* __restrict__ w3,
    const float* __restrict__ b3, float* __restrict__ out,
    int H, int W, int nu, int interleave)
{
    __shared__ float s_in[16][400];
    __shared__ float s_w[16 * 25];

    int z = blockIdx.z;
    int u = z % nu;
    int b = z / nu;
    int tid = threadIdx.x;
    int x0 = blockIdx.x * 16, y0 = blockIdx.y * 16;
    int ty = tid >> 4, tx = tid & 15;
    const float* inz = in + (size_t)z * 32 * H * W;

    float acc = b3[u];

    for (int icb = 0; icb < 32; icb += 16) {
        __syncthreads();
        for (int i = tid; i < 6400; i += 256) {
            int ic = i / 400;
            int r = i - ic * 400;
            int iy = r / 20, ix = r - iy * 20;
            int gy = y0 + iy - 2, gx = x0 + ix - 2;
            float v = 0.f;
            if (gy >= 0 && gy < H && gx >= 0 && gx < W)
                v = inz[(size_t)(icb + ic) * H * W + (size_t)gy * W + gx];
            s_in[ic][r] = v;
        }
        for (int i = tid; i < 400; i += 256)
            s_w[i] = w3[(size_t)u * 800 + icb * 25 + i];
        __syncthreads();

        for (int ic = 0; ic < 16; ic++) {
#pragma unroll
            for (int dy = 0; dy < 5; dy++)
#pragma unroll
                for (int dx = 0; dx < 5; dx++)
                    acc += s_in[ic][(ty + dy) * 20 + tx + dx] * s_w[ic * 25 + dy * 5 + dx];
        }
    }

    int y = y0 + ty, x = x0 + tx;
    if (interleave) {
        int uy = u >> 1, ux = u & 1;
        out[(size_t)b * 4 * H * W + (size_t)(2 * y + uy) * (2 * W) + 2 * x + ux] = acc;
    } else {
        out[(size_t)b * H * W + (size_t)y * W + x] = acc;
    }
}

// ---------------------------------------------------------------------------
// msf_in = up8(x2) + up4(x4) + up2(x8) + x16  (bilinear half-pixel, clamp)
// ---------------------------------------------------------------------------
__device__ __forceinline__ float bilin(const float* __restrict__ p, int N,
                                       float inv_s, int y, int x) {
    float sy = (y + 0.5f) * inv_s - 0.5f;
    float sx = (x + 0.5f) * inv_s - 0.5f;
    float fy0 = floorf(sy), fx0 = floorf(sx);
    float fy = sy - fy0, fx = sx - fx0;
    int y0 = (int)fy0, x0 = (int)fx0;
    int y0c = min(max(y0, 0), N - 1);
    int y1c = min(max(y0 + 1, 0), N - 1);
    int x0c = min(max(x0, 0), N - 1);
    int x1c = min(max(x0 + 1, 0), N - 1);
    float v00 = p[(size_t)y0c * N + x0c];
    float v01 = p[(size_t)y0c * N + x1c];
    float v10 = p[(size_t)y1c * N + x0c];
    float v11 = p[(size_t)y1c * N + x1c];
    return (1.f - fy) * ((1.f - fx) * v00 + fx * v01) +
           fy * ((1.f - fx) * v10 + fx * v11);
}

__global__ void msf_in_kernel(const float* __restrict__ x2,
                              const float* __restrict__ x4,
                              const float* __restrict__ x8,
                              const float* __restrict__ x16,
                              float* __restrict__ out) {
    int idx = blockIdx.x * 256 + threadIdx.x;
    if (idx >= 2 * 1024 * 1024) return;
    int b = idx >> 20;
    int r = idx & 0xFFFFF;
    int y = r >> 10, x = r & 1023;
    float v = x16[idx];
    v += bilin(x2 + (size_t)b * 128 * 128, 128, 0.125f, y, x);
    v += bilin(x4 + (size_t)b * 256 * 256, 256, 0.25f, y, x);
    v += bilin(x8 + (size_t)b * 512 * 512, 512, 0.5f, y, x);
    out[idx] = v;
}

// ---------------------------------------------------------------------------
// Host orchestration
// ---------------------------------------------------------------------------
extern "C" void kernel_launch(void* const* d_in, const int* in_sizes, int n_in,
                              void* d_out, int out_size) {
    const float* image = (const float*)d_in[0];
    const float* w1 = (const float*)d_in[1];
    const float* b1 = (const float*)d_in[2];
    const float* w2 = (const float*)d_in[3];
    const float* b2 = (const float*)d_in[4];
    const float* w3 = (const float*)d_in[5];
    const float* b3 = (const float*)d_in[6];
    float* out = (float*)d_out;

    float *t1, *t2, *msf, *w1t, *w2t;
    cudaGetSymbolAddress((void**)&t1, g_t1);
    cudaGetSymbolAddress((void**)&t2, g_t2);
    cudaGetSymbolAddress((void**)&msf, g_msf);
    cudaGetSymbolAddress((void**)&w1t, g_w1t);
    cudaGetSymbolAddress((void**)&w2t, g_w2t);

    prep_weights_kernel<<<(17 * 64 * 25 * 32 + 255) / 256, 256>>>(w1, w2);

    float* ox2 = out + 0;
    float* ox4 = out + 32768;
    float* ox8 = out + 163840;
    float* ox16 = out + 688128;
    float* omsf = out + 2785280;

    auto run_stage = [&](const float* inp, int H, int W, int ubase,
                         float* outp, int nu, int il) {
        dim3 g(W / 16, H / 16, 2 * nu);
        conv1_kernel<<<g, 256>>>(inp, w1t + (size_t)ubase * 5184,
                                 b1 + (size_t)ubase * 64, t1, H, W, nu);
        conv2_mma_kernel<<<g, 256>>>(t1, w2t + (size_t)ubase * 51200,
                                     b2 + (size_t)ubase * 32, t2, H, W, nu);
        conv3_kernel<<<g, 256>>>(t2, w3 + (size_t)ubase * 800,
                                 b3 + ubase, outp, H, W, nu, il);
    };

    run_stage(image, 64, 64, 0, ox2, 4, 1);
    run_stage(ox2, 128, 128, 4, ox4, 4, 1);
    run_stage(ox4, 256, 256, 8, ox8, 4, 1);
    run_stage(ox8, 512, 512, 12, ox16, 4, 1);

    msf_in_kernel<<<(2 * 1024 * 1024) / 256, 256>>>(ox2, ox4, ox8, ox16, msf);

    run_stage(msf, 1024, 1024, 16, omsf, 1, 0);
}

// round 3
// speedup vs baseline: 3.2178x; 1.6106x over previous
#include <cuda_runtime.h>
#include <cuda_fp16.h>
#include <cstdint>

// ---------------------------------------------------------------------------
// DSDMSR multi-scale SRCNN cascade.
// conv1 (9x9,1->64) fp32 -> fp16 out; conv2 (5x5,64->32) fp16 mma.sync m16n8k16;
// conv3 (5x5,32->1) fp32.
// ---------------------------------------------------------------------------

__device__ __half g_t1h[134217728];          // conv1 out, [z][H][W][64] fp16 (256MB)
__device__ float  g_t2[67108864];            // conv2 out, [z][32][H][W] fp32 (256MB)
__device__ float  g_msf[2 * 1024 * 1024];
__device__ float  g_w1t[17 * 81 * 64];       // [u][tap][oc] fp32
__device__ __half g_w2h[17 * 4 * 25 * 2 * 32 * 8];  // fragment-major fp16

// ---------------------------------------------------------------------------
// Weight prep.
// w2 fragment-major: [u][ic-chunk(4)][tap(25)][m-tile(2)][lane(32)][8 halves]
// lane l: g=l>>2, t=l&3; halves order = {A[g][2t],A[g][2t+1],A[g+8][2t],
//   A[g+8][2t+1],A[g][2t+8],A[g][2t+9],A[g+8][2t+8],A[g+8][2t+9]}
// where A row = oc (m*16+...), col = ic within 16-chunk.
// ---------------------------------------------------------------------------
__global__ void prep_weights_kernel(const float* __restrict__ w1,
                                    const float* __restrict__ w2) {
    int idx = blockIdx.x * 256 + threadIdx.x;
    if (idx < 17 * 81 * 64) {
        int u = idx / (81 * 64);
        int r = idx - u * 81 * 64;
        int tap = r / 64;
        int oc = r - tap * 64;
        g_w1t[idx] = w1[(u * 64 + oc) * 81 + tap];
    }
    if (idx < 17 * 4 * 25 * 2 * 32) {
        int l = idx & 31;
        int m = (idx >> 5) & 1;
        int rest = idx >> 6;             // (u*4+ch)*25 + tap
        int tap = rest % 25;
        int rest2 = rest / 25;
        int ch = rest2 & 3;
        int u = rest2 >> 2;
        int g = l >> 2, t = l & 3;
        int oc0 = m * 16 + g;
        int ic0 = ch * 16;
        __half h[8];
#pragma unroll
        for (int q = 0; q < 8; q++) {
            int oc = oc0 + ((q >> 1) & 1) * 8;
            int ic = ic0 + 2 * t + (q & 1) + (q >> 2) * 8;
            h[q] = __float2half_rn(w2[((size_t)(u * 32 + oc) * 64 + ic) * 25 + tap]);
        }
        __half* dst = g_w2h + (size_t)idx * 8;
#pragma unroll
        for (int q = 0; q < 8; q++) dst[q] = h[q];
    }
}

// ---------------------------------------------------------------------------
// conv1: 9x9, 1 -> 64, ReLU; fp32 math, fp16 output in [z][H][W][64].
// ---------------------------------------------------------------------------
__global__ __launch_bounds__(256) void conv1_kernel(
    const float* __restrict__ in, const float* __restrict__ wt,
    const float* __restrict__ bias, __half* __restrict__ out,
    int H, int W, int nu)
{
    __shared__ float s_in[24 * 24];
    __shared__ float s_w[81 * 64];

    int z = blockIdx.z;
    int u = z % nu;
    int b = z / nu;
    int tid = threadIdx.x;
    int x0 = blockIdx.x * 16, y0 = blockIdx.y * 16;
    const float* inb = in + (size_t)b * H * W;
    const float* wu = wt + (size_t)u * 5184;

    for (int i = tid; i < 576; i += 256) {
        int iy = i / 24, ix = i - iy * 24;
        int gy = y0 + iy - 4, gx = x0 + ix - 4;
        float v = 0.f;
        if (gy >= 0 && gy < H && gx >= 0 && gx < W) v = inb[(size_t)gy * W + gx];
        s_in[i] = v;
    }
    for (int i = tid; i < 5184; i += 256) s_w[i] = wu[i];
    __syncthreads();

    int ocg = tid >> 6;
    int pt = tid & 63;
    int row = pt >> 2;
    int cgx = (pt & 3) * 4;

    float acc[4][16];
#pragma unroll
    for (int j = 0; j < 4; j++)
#pragma unroll
        for (int c = 0; c < 16; c++) acc[j][c] = 0.f;

    for (int dy = 0; dy < 9; dy++) {
        const float* ipb = &s_in[(row + dy) * 24 + cgx];
        const float* wpb = &s_w[dy * 9 * 64 + ocg * 16];
#pragma unroll
        for (int dx = 0; dx < 9; dx++) {
            float iv[4];
#pragma unroll
            for (int j = 0; j < 4; j++) iv[j] = ipb[dx + j];
            const float* wp = wpb + dx * 64;
            float4 w0 = *(const float4*)(wp);
            float4 w1v = *(const float4*)(wp + 4);
            float4 w2v = *(const float4*)(wp + 8);
            float4 w3v = *(const float4*)(wp + 12);
            float wv[16] = {w0.x, w0.y, w0.z, w0.w, w1v.x, w1v.y, w1v.z, w1v.w,
                            w2v.x, w2v.y, w2v.z, w2v.w, w3v.x, w3v.y, w3v.z, w3v.w};
#pragma unroll
            for (int j = 0; j < 4; j++)
#pragma unroll
                for (int c = 0; c < 16; c++) acc[j][c] += iv[j] * wv[c];
        }
    }

    float bvv[16];
#pragma unroll
    for (int c = 0; c < 16; c++) bvv[c] = bias[u * 64 + ocg * 16 + c];

    int y = y0 + row;
#pragma unroll
    for (int j = 0; j < 4; j++) {
        __align__(16) __half h[16];
#pragma unroll
        for (int c = 0; c < 16; c++)
            h[c] = __float2half_rn(fmaxf(acc[j][c] + bvv[c], 0.f));
        __half* op = out + (((size_t)z * H + y) * W + x0 + cgx + j) * 64 + ocg * 16;
        *(uint4*)op = *(uint4*)h;
        *(uint4*)(op + 8) = *(uint4*)(h + 8);
    }
}

// ---------------------------------------------------------------------------
// conv2: 5x5, 64 -> 32, ReLU via fp16 mma.sync.m16n8k16.
// Block 256 thr (8 warps), 16x16 px tile, 32 oc.
// Warp: rows 2w,2w+1 (32 px) x 32 oc = 2 M-tiles x 4 N-tiles; K = ic chunks of 16.
// ---------------------------------------------------------------------------
__device__ __forceinline__ void mma_f16(float c[4], const uint4& a,
                                        unsigned b0, unsigned b1) {
    asm volatile(
        "mma.sync.aligned.m16n8k16.row.col.f32.f16.f16.f32 "
        "{%0,%1,%2,%3}, {%4,%5,%6,%7}, {%8,%9}, {%0,%1,%2,%3};"
        : "+f"(c[0]), "+f"(c[1]), "+f"(c[2]), "+f"(c[3])
        : "r"(a.x), "r"(a.y), "r"(a.z), "r"(a.w), "r"(b0), "r"(b1));
}

__global__ __launch_bounds__(256) void conv2_mma_kernel(
    const __half* __restrict__ in,    // [z][H][W][64] fp16
    const __half* __restrict__ wt,    // [nu][4][25][2][32][8] fragment-major
    const float* __restrict__ bias,   // [nu][32]
    float* __restrict__ out,          // [z][32][H][W] fp32
    int H, int W, int nu)
{
    __shared__ __half s_raw[400 * 16];       // [site=20x20][16 ic]
    __shared__ __half s_w[25 * 2 * 32 * 8];  // [tap][m][lane][8]

    int z = blockIdx.z;
    int u = z % nu;
    int tid = threadIdx.x;
    int warp = tid >> 5;
    int lane = tid & 31;
    int x0 = blockIdx.x * 16, y0 = blockIdx.y * 16;
    const __half* inz = in + (size_t)z * H * W * 64;
    const __half* wu = wt + (size_t)u * 4 * 12800;

    int g = lane >> 2, t = lane & 3;
    int r0 = warp * 2;

    int bbase[4];
#pragma unroll
    for (int j = 0; j < 4; j++)
        bbase[j] = ((r0 + (j >> 1)) * 20 + (j & 1) * 8 + g) * 16 + 2 * t;

    float c[2][4][4];
#pragma unroll
    for (int m = 0; m < 2; m++)
#pragma unroll
        for (int j = 0; j < 4; j++)
#pragma unroll
            for (int q = 0; q < 4; q++) c[m][j][q] = 0.f;

    for (int ch = 0; ch < 4; ch++) {
        __syncthreads();
        // halo: 400 sites x 16 ic, as 800 16B transfers
#pragma unroll
        for (int l = 0; l < 4; l++) {
            int i = tid + l * 256;
            if (i < 800) {
                int site = i >> 1, part = i & 1;
                int py = site / 20, px = site - py * 20;
                int gy = y0 + py - 2, gx = x0 + px - 2;
                uint4 v = make_uint4(0, 0, 0, 0);
                if (gy >= 0 && gy < H && gx >= 0 && gx < W)
                    v = *(const uint4*)&inz[((size_t)gy * W + gx) * 64 + ch * 16 + part * 8];
                *(uint4*)&s_raw[site * 16 + part * 8] = v;
            }
        }
        // weights: 25*2*32*8 halves = 1600 16B transfers, linear copy
        const uint4* wsrc = (const uint4*)(wu + (size_t)ch * 12800);
#pragma unroll
        for (int l = 0; l < 7; l++) {
            int i = tid + l * 256;
            if (i < 1600) ((uint4*)s_w)[i] = wsrc[i];
        }
        __syncthreads();

#pragma unroll
        for (int dy = 0; dy < 5; dy++) {
#pragma unroll
            for (int dx = 0; dx < 5; dx++) {
                int tap = dy * 5 + dx;
                int toff = (dy * 20 + dx) * 16;
                uint4 a0 = *(const uint4*)&s_w[(size_t)(tap * 2 + 0) * 256 + lane * 8];
                uint4 a1 = *(const uint4*)&s_w[(size_t)(tap * 2 + 1) * 256 + lane * 8];
#pragma unroll
                for (int j = 0; j < 4; j++) {
                    unsigned b0 = *(const unsigned*)&s_raw[bbase[j] + toff];
                    unsigned b1 = *(const unsigned*)&s_raw[bbase[j] + toff + 8];
                    mma_f16(c[0][j], a0, b0, b1);
                    mma_f16(c[1][j], a1, b0, b1);
                }
            }
        }
    }

    // epilogue: oc = m*16 + g (+8), y = y0 + r0 + (j>>1), x = x0 + (j&1)*8 + 2*t
#pragma unroll
    for (int m = 0; m < 2; m++) {
        int oc0 = m * 16 + g;
        float bv0 = bias[u * 32 + oc0];
        float bv1 = bias[u * 32 + oc0 + 8];
#pragma unroll
        for (int j = 0; j < 4; j++) {
            int y = y0 + r0 + (j >> 1);
            int x = x0 + (j & 1) * 8 + 2 * t;
            float2 v0, v1;
            v0.x = fmaxf(c[m][j][0] + bv0, 0.f);
            v0.y = fmaxf(c[m][j][1] + bv0, 0.f);
            v1.x = fmaxf(c[m][j][2] + bv1, 0.f);
            v1.y = fmaxf(c[m][j][3] + bv1, 0.f);
            *(float2*)(out + ((size_t)z * 32 + oc0) * H * W + (size_t)y * W + x) = v0;
            *(float2*)(out + ((size_t)z * 32 + oc0 + 8) * H * W + (size_t)y * W + x) = v1;
        }
    }
}

// ---------------------------------------------------------------------------
// conv3: 5x5, 32 -> 1, no ReLU, optional 2x2 interleaved scatter.
// ---------------------------------------------------------------------------
__global__ __launch_bounds__(256) void conv3_kernel(
    const float* __restrict__ in, const float* __restrict__ w3,
    const float* __restrict__ b3, float* __restrict__ out,
    int H, int W, int nu, int interleave)
{
    __shared__ float s_in[16][400];
    __shared__ float s_w[16 * 25];

    int z = blockIdx.z;
    int u = z % nu;
    int b = z / nu;
    int tid = threadIdx.x;
    int x0 = blockIdx.x * 16, y0 = blockIdx.y * 16;
    int ty = tid >> 4, tx = tid & 15;
    const float* inz = in + (size_t)z * 32 * H * W;

    float acc = b3[u];

    for (int icb = 0; icb < 32; icb += 16) {
        __syncthreads();
        for (int i = tid; i < 6400; i += 256) {
            int ic = i / 400;
            int r = i - ic * 400;
            int iy = r / 20, ix = r - iy * 20;
            int gy = y0 + iy - 2, gx = x0 + ix - 2;
            float v = 0.f;
            if (gy >= 0 && gy < H && gx >= 0 && gx < W)
                v = inz[(size_t)(icb + ic) * H * W + (size_t)gy * W + gx];
            s_in[ic][r] = v;
        }
        for (int i = tid; i < 400; i += 256)
            s_w[i] = w3[(size_t)u * 800 + icb * 25 + i];
        __syncthreads();

        for (int ic = 0; ic < 16; ic++) {
#pragma unroll
            for (int dy = 0; dy < 5; dy++)
#pragma unroll
                for (int dx = 0; dx < 5; dx++)
                    acc += s_in[ic][(ty + dy) * 20 + tx + dx] * s_w[ic * 25 + dy * 5 + dx];
        }
    }

    int y = y0 + ty, x = x0 + tx;
    if (interleave) {
        int uy = u >> 1, ux = u & 1;
        out[(size_t)b * 4 * H * W + (size_t)(2 * y + uy) * (2 * W) + 2 * x + ux] = acc;
    } else {
        out[(size_t)b * H * W + (size_t)y * W + x] = acc;
    }
}

// ---------------------------------------------------------------------------
// msf_in = up8(x2) + up4(x4) + up2(x8) + x16  (bilinear half-pixel, clamp)
// ---------------------------------------------------------------------------
__device__ __forceinline__ float bilin(const float* __restrict__ p, int N,
                                       float inv_s, int y, int x) {
    float sy = (y + 0.5f) * inv_s - 0.5f;
    float sx = (x + 0.5f) * inv_s - 0.5f;
    float fy0 = floorf(sy), fx0 = floorf(sx);
    float fy = sy - fy0, fx = sx - fx0;
    int y0 = (int)fy0, x0 = (int)fx0;
    int y0c = min(max(y0, 0), N - 1);
    int y1c = min(max(y0 + 1, 0), N - 1);
    int x0c = min(max(x0, 0), N - 1);
    int x1c = min(max(x0 + 1, 0), N - 1);
    float v00 = p[(size_t)y0c * N + x0c];
    float v01 = p[(size_t)y0c * N + x1c];
    float v10 = p[(size_t)y1c * N + x0c];
    float v11 = p[(size_t)y1c * N + x1c];
    return (1.f - fy) * ((1.f - fx) * v00 + fx * v01) +
           fy * ((1.f - fx) * v10 + fx * v11);
}

__global__ void msf_in_kernel(const float* __restrict__ x2,
                              const float* __restrict__ x4,
                              const float* __restrict__ x8,
                              const float* __restrict__ x16,
                              float* __restrict__ out) {
    int idx = blockIdx.x * 256 + threadIdx.x;
    if (idx >= 2 * 1024 * 1024) return;
    int b = idx >> 20;
    int r = idx & 0xFFFFF;
    int y = r >> 10, x = r & 1023;
    float v = x16[idx];
    v += bilin(x2 + (size_t)b * 128 * 128, 128, 0.125f, y, x);
    v += bilin(x4 + (size_t)b * 256 * 256, 256, 0.25f, y, x);
    v += bilin(x8 + (size_t)b * 512 * 512, 512, 0.5f, y, x);
    out[idx] = v;
}

// ---------------------------------------------------------------------------
// Host orchestration
// ---------------------------------------------------------------------------
extern "C" void kernel_launch(void* const* d_in, const int* in_sizes, int n_in,
                              void* d_out, int out_size) {
    const float* image = (const float*)d_in[0];
    const float* w1 = (const float*)d_in[1];
    const float* b1 = (const float*)d_in[2];
    const float* w2 = (const float*)d_in[3];
    const float* b2 = (const float*)d_in[4];
    const float* w3 = (const float*)d_in[5];
    const float* b3 = (const float*)d_in[6];
    float* out = (float*)d_out;

    __half *t1h, *w2h;
    float *t2, *msf, *w1t;
    cudaGetSymbolAddress((void**)&t1h, g_t1h);
    cudaGetSymbolAddress((void**)&t2, g_t2);
    cudaGetSymbolAddress((void**)&msf, g_msf);
    cudaGetSymbolAddress((void**)&w1t, g_w1t);
    cudaGetSymbolAddress((void**)&w2h, g_w2h);

    prep_weights_kernel<<<(17 * 4 * 25 * 2 * 32 + 255) / 256, 256>>>(w1, w2);

    float* ox2 = out + 0;
    float* ox4 = out + 32768;
    float* ox8 = out + 163840;
    float* ox16 = out + 688128;
    float* omsf = out + 2785280;

    auto run_stage = [&](const float* inp, int H, int W, int ubase,
                         float* outp, int nu, int il) {
        dim3 g(W / 16, H / 16, 2 * nu);
        conv1_kernel<<<g, 256>>>(inp, w1t + (size_t)ubase * 5184,
                                 b1 + (size_t)ubase * 64, t1h, H, W, nu);
        conv2_mma_kernel<<<g, 256>>>(t1h, w2h + (size_t)ubase * 4 * 12800,
                                     b2 + (size_t)ubase * 32, t2, H, W, nu);
        conv3_kernel<<<g, 256>>>(t2, w3 + (size_t)ubase * 800,
                                 b3 + ubase, outp, H, W, nu, il);
    };

    run_stage(image, 64, 64, 0, ox2, 4, 1);
    run_stage(ox2, 128, 128, 4, ox4, 4, 1);
    run_stage(ox4, 256, 256, 8, ox8, 4, 1);
    run_stage(ox8, 512, 512, 12, ox16, 4, 1);

    msf_in_kernel<<<(2 * 1024 * 1024) / 256, 256>>>(ox2, ox4, ox8, ox16, msf);

    run_stage(msf, 1024, 1024, 16, omsf, 1, 0);
}